// round 1
// baseline (speedup 1.0000x reference)
#include <cuda_runtime.h>
#include <math.h>

#define NT 256

// Fused TT-network:  y = log_softmax( x_pad @ W1_tt @ W2_tt )
// Key identity: (TT-matrix W1) @ (TT-matrix W2 with matching modes) is a TT
// matrix with cores G_k = contract_n(c1_k, c2_k), ranks kron'd (3*3=9).
// x is zero-padded 177->3072 => only m1=m2=0 contribute => effective W is 256x10.
//
// Single block, everything in static shared memory.
__global__ __launch_bounds__(NT) void tt_fused_kernel(
    const float* __restrict__ x,     // (64,177)
    const float* __restrict__ c1_0,  // (1,3,10,3)
    const float* __restrict__ c1_1,  // (3,4,20,3)
    const float* __restrict__ c1_2,  // (3,8,50,3)
    const float* __restrict__ c1_3,  // (3,4,20,3)
    const float* __restrict__ c1_4,  // (3,8,10,1)
    const float* __restrict__ c2_0,  // (1,10,1,3)
    const float* __restrict__ c2_1,  // (3,20,2,3)
    const float* __restrict__ c2_2,  // (3,50,5,3)
    const float* __restrict__ c2_3,  // (3,20,1,3)
    const float* __restrict__ c2_4,  // (3,10,1,1)
    float* __restrict__ out)         // (64,10)
{
    // combined-core and chain buffers
    __shared__ float sG1[648];    // [r1(9), m2(4), p2(2), r2(9)]
    __shared__ float sG2[3240];   // [u(72) = (a2,m3,a3)] x [v(45) = (b2,p3,b3)]
    __shared__ float sG3[324];    // [r3(9), m4(4), r4(9)]
    __shared__ float sG4[72];     // [r4(9), m5(8)]
    __shared__ float sA1[9];
    __shared__ float sA2[18];     // [p2(2), r2(9)]
    __shared__ float sA3[720];    // [m3(8), c(10), r3(9)]
    __shared__ float sBUF[5850];  // phase A: sC1(3600)+sC2(2250); phase B: A4(2880)+W(2560)
    __shared__ float sLog[640];

    float* sC1 = sBUF;            // staged c1_2
    float* sC2 = sBUF + 3600;     // staged c2_2
    float* sA4 = sBUF;            // [m3(8), m4(4), c(10), r4(9)]  (reuses sC1 space)
    float* sW  = sBUF + 2880;     // [j(256), c(10)]               (reuses tail)

    const int tid = threadIdx.x;

    // ---------- Phase 0: stage big cores; build G1, G3, G4, A1 ----------
    for (int i = tid; i < 3600; i += NT) sC1[i] = c1_2[i];
    for (int i = tid; i < 2250; i += NT) sC2[i] = c2_2[i];

    // G1[r1,m2,p2,r2] = sum_n c1_1[a1,m2,n,a2] * c2_1[b1,n,p2,b2]
    for (int o = tid; o < 648; o += NT) {
        int r2 = o % 9; int rest = o / 9;
        int p2 = rest % 2; rest /= 2;
        int m2 = rest % 4; int r1 = rest / 4;
        int a1 = r1 / 3, b1 = r1 % 3, a2 = r2 / 3, b2 = r2 % 3;
        const float* pa = c1_1 + (a1 * 4 + m2) * 60 + a2;      // n-stride 3
        const float* pb = c2_1 + b1 * 120 + p2 * 3 + b2;       // n-stride 6
        float acc = 0.f;
        #pragma unroll
        for (int n = 0; n < 20; n++) acc += pa[n * 3] * pb[n * 6];
        sG1[o] = acc;
    }
    // G3[r3,m4,r4] = sum_n c1_3[a3,m4,n,a4] * c2_3[b3,n,0,b4]
    for (int o = tid; o < 324; o += NT) {
        int r4 = o % 9; int rest = o / 9;
        int m4 = rest % 4; int r3 = rest / 4;
        int a3 = r3 / 3, b3 = r3 % 3, a4 = r4 / 3, b4 = r4 % 3;
        const float* pa = c1_3 + (a3 * 4 + m4) * 60 + a4;      // n-stride 3
        const float* pb = c2_3 + b3 * 60 + b4;                 // n-stride 3
        float acc = 0.f;
        #pragma unroll
        for (int n = 0; n < 20; n++) acc += pa[n * 3] * pb[n * 3];
        sG3[o] = acc;
    }
    // G4[r4,m5] = sum_n c1_4[a4,m5,n,0] * c2_4[b4,n,0,0]
    for (int o = tid; o < 72; o += NT) {
        int m5 = o % 8, r4 = o / 8;
        int a4 = r4 / 3, b4 = r4 % 3;
        const float* pa = c1_4 + (a4 * 8 + m5) * 10;
        const float* pb = c2_4 + b4 * 10;
        float acc = 0.f;
        #pragma unroll
        for (int n = 0; n < 10; n++) acc += pa[n] * pb[n];
        sG4[r4 * 8 + m5] = acc;
    }
    // A1[r1] = sum_n c1_0[0,0,n,a1] * c2_0[0,n,0,b1]   (m1=0 only)
    if (tid < 9) {
        int a1 = tid / 3, b1 = tid % 3;
        float acc = 0.f;
        #pragma unroll
        for (int n = 0; n < 10; n++) acc += c1_0[n * 3 + a1] * c2_0[n * 3 + b1];
        sA1[tid] = acc;
    }
    __syncthreads();

    // ---------- Phase 1: G2 (72x45x50 matmul, 4x3 register tiles) + A2 ----------
    if (tid < 18) {  // A2[p2,r2] = sum_r1 A1[r1]*G1[r1,0,p2,r2]
        int r2 = tid % 9, p2 = tid / 9;
        float acc = 0.f;
        #pragma unroll
        for (int r1 = 0; r1 < 9; r1++)
            acc += sA1[r1] * sG1[(r1 * 8 + p2) * 9 + r2];
        sA2[p2 * 9 + r2] = acc;
    }
    for (int t = tid; t < 270; t += NT) {   // 18 u-tiles x 15 v-tiles
        int u0 = (t / 15) * 4, v0 = (t % 15) * 3;
        float acc[4][3] = {};
        int abase[4], bbase[3];
        #pragma unroll
        for (int i = 0; i < 4; i++) { int u = u0 + i; abase[i] = (u / 3) * 150 + (u % 3); }
        #pragma unroll
        for (int j = 0; j < 3; j++) { int v = v0 + j; bbase[j] = (v / 15) * 750 + (v % 15); }
        #pragma unroll 5
        for (int k = 0; k < 50; k++) {
            float a[4], b[3];
            #pragma unroll
            for (int i = 0; i < 4; i++) a[i] = sC1[abase[i] + k * 3];
            #pragma unroll
            for (int j = 0; j < 3; j++) b[j] = sC2[bbase[j] + k * 15];
            #pragma unroll
            for (int i = 0; i < 4; i++)
                #pragma unroll
                for (int j = 0; j < 3; j++) acc[i][j] += a[i] * b[j];
        }
        #pragma unroll
        for (int i = 0; i < 4; i++)
            #pragma unroll
            for (int j = 0; j < 3; j++) sG2[(u0 + i) * 45 + (v0 + j)] = acc[i][j];
    }
    __syncthreads();

    // ---------- Phase 2: A3[m3,c,r3] = sum_{a2,b2} A2[p2,(a2,b2)] * G2 ----------
    for (int o = tid; o < 720; o += NT) {
        int r3 = o % 9; int rest = o / 9;
        int c = rest % 10; int m3 = rest / 10;
        int p2 = c / 5, p3 = c % 5;
        int a3 = r3 / 3, b3 = r3 % 3;
        float acc = 0.f;
        #pragma unroll
        for (int a2 = 0; a2 < 3; a2++)
            #pragma unroll
            for (int b2 = 0; b2 < 3; b2++)
                acc += sA2[p2 * 9 + a2 * 3 + b2]
                     * sG2[(a2 * 24 + m3 * 3 + a3) * 45 + (b2 * 15 + p3 * 3 + b3)];
        sA3[o] = acc;
    }
    __syncthreads();

    // ---------- Phase 3: A4[m3,m4,c,r4] = sum_r3 A3[m3,c,r3]*G3[r3,m4,r4] ----------
    // (overwrites staged c1_2 region; it is dead now)
    for (int o = tid; o < 2880; o += NT) {
        int r4 = o % 9; int rest = o / 9;
        int c = rest % 10; rest /= 10;
        int m4 = rest % 4; int m3 = rest / 4;
        float acc = 0.f;
        #pragma unroll
        for (int r3 = 0; r3 < 9; r3++)
            acc += sA3[(m3 * 10 + c) * 9 + r3] * sG3[(r3 * 4 + m4) * 9 + r4];
        sA4[o] = acc;
    }
    __syncthreads();

    // ---------- Phase 4: W[j,c] = sum_r4 A4[m3,m4,c,r4]*G4[r4,m5], j=m3*32+m4*8+m5 ----------
    for (int o = tid; o < 2560; o += NT) {
        int c = o % 10; int j = o / 10;
        int m5 = j % 8; int m4 = (j / 8) % 4; int m3 = j / 32;
        float acc = 0.f;
        #pragma unroll
        for (int r4 = 0; r4 < 9; r4++)
            acc += sA4[((m3 * 4 + m4) * 10 + c) * 9 + r4] * sG4[r4 * 8 + m5];
        sW[o] = acc;
    }
    __syncthreads();

    // ---------- Phase 5: logits[b,c] = sum_{j<177} x[b,j] * W[j,c] ----------
    for (int o = tid; o < 640; o += NT) {
        int c = o % 10; int b = o / 10;
        const float* xr = x + b * 177;
        float acc = 0.f;
        #pragma unroll 3
        for (int j = 0; j < 177; j++)
            acc += xr[j] * sW[j * 10 + c];
        sLog[o] = acc;
    }
    __syncthreads();

    // ---------- Phase 6: log_softmax per row ----------
    if (tid < 64) {
        float v[10], m = -INFINITY;
        #pragma unroll
        for (int c = 0; c < 10; c++) { v[c] = sLog[tid * 10 + c]; m = fmaxf(m, v[c]); }
        float s = 0.f;
        #pragma unroll
        for (int c = 0; c < 10; c++) s += __expf(v[c] - m);
        float lse = m + __logf(s);
        #pragma unroll
        for (int c = 0; c < 10; c++) out[tid * 10 + c] = v[c] - lse;
    }
}

extern "C" void kernel_launch(void* const* d_in, const int* in_sizes, int n_in,
                              void* d_out, int out_size) {
    const float* x    = (const float*)d_in[0];
    const float* c1_0 = (const float*)d_in[1];
    const float* c1_1 = (const float*)d_in[2];
    const float* c1_2 = (const float*)d_in[3];
    const float* c1_3 = (const float*)d_in[4];
    const float* c1_4 = (const float*)d_in[5];
    const float* c2_0 = (const float*)d_in[6];
    const float* c2_1 = (const float*)d_in[7];
    const float* c2_2 = (const float*)d_in[8];
    const float* c2_3 = (const float*)d_in[9];
    const float* c2_4 = (const float*)d_in[10];
    float* out = (float*)d_out;

    tt_fused_kernel<<<1, NT>>>(x, c1_0, c1_1, c1_2, c1_3, c1_4,
                               c2_0, c2_1, c2_2, c2_3, c2_4, out);
}

// round 5
// speedup vs baseline: 1.7386x; 1.7386x over previous
#include <cuda_runtime.h>
#include <math.h>

#define NT 1024

// Fused TT-network:  y = log_softmax( x_pad @ W1_tt @ W2_tt )
// TT x TT (matching modes) = TT with cores G_k = contract_n(c1_k, c2_k),
// ranks kron'd (3*3=9). Zero-pad 177->3072 => only m1=m2=0 contribute =>
// effective dense weight is W[256,10]; only j<177 rows ever touched.
//
// EXACT Round-1 kernel text (which passed at rel_err 3.2e-7); the ONLY change
// is NT 256 -> 1024. All phases are grid-stride or tid<K guarded, so the
// computed values are bit-identical; we just get 32 warps for latency hiding.
__global__ __launch_bounds__(NT) void tt_fused_kernel(
    const float* __restrict__ x,     // (64,177)
    const float* __restrict__ c1_0,  // (1,3,10,3)
    const float* __restrict__ c1_1,  // (3,4,20,3)
    const float* __restrict__ c1_2,  // (3,8,50,3)
    const float* __restrict__ c1_3,  // (3,4,20,3)
    const float* __restrict__ c1_4,  // (3,8,10,1)
    const float* __restrict__ c2_0,  // (1,10,1,3)
    const float* __restrict__ c2_1,  // (3,20,2,3)
    const float* __restrict__ c2_2,  // (3,50,5,3)
    const float* __restrict__ c2_3,  // (3,20,1,3)
    const float* __restrict__ c2_4,  // (3,10,1,1)
    float* __restrict__ out)         // (64,10)
{
    __shared__ float sG1[648];    // [r1(9), m2(4), p2(2), r2(9)]
    __shared__ float sG2[3240];   // [u(72) = (a2,m3,a3)] x [v(45) = (b2,p3,b3)]
    __shared__ float sG3[324];    // [r3(9), m4(4), r4(9)]
    __shared__ float sG4[72];     // [r4(9), m5(8)]
    __shared__ float sA1[9];
    __shared__ float sA2[18];     // [p2(2), r2(9)]
    __shared__ float sA3[720];    // [m3(8), c(10), r3(9)]
    __shared__ float sBUF[5850];  // phase A: sC1(3600)+sC2(2250); phase B: A4(2880)+W(2560)
    __shared__ float sLog[640];

    float* sC1 = sBUF;            // staged c1_2
    float* sC2 = sBUF + 3600;     // staged c2_2
    float* sA4 = sBUF;            // [m3(8), m4(4), c(10), r4(9)]  (reuses sC1 space)
    float* sW  = sBUF + 2880;     // [j(256), c(10)]               (reuses tail)

    const int tid = threadIdx.x;

    // ---------- Phase 0: stage big cores; build G1, G3, G4, A1 ----------
    for (int i = tid; i < 3600; i += NT) sC1[i] = c1_2[i];
    for (int i = tid; i < 2250; i += NT) sC2[i] = c2_2[i];

    // G1[r1,m2,p2,r2] = sum_n c1_1[a1,m2,n,a2] * c2_1[b1,n,p2,b2]
    for (int o = tid; o < 648; o += NT) {
        int r2 = o % 9; int rest = o / 9;
        int p2 = rest % 2; rest /= 2;
        int m2 = rest % 4; int r1 = rest / 4;
        int a1 = r1 / 3, b1 = r1 % 3, a2 = r2 / 3, b2 = r2 % 3;
        const float* pa = c1_1 + (a1 * 4 + m2) * 60 + a2;      // n-stride 3
        const float* pb = c2_1 + b1 * 120 + p2 * 3 + b2;       // n-stride 6
        float acc = 0.f;
        #pragma unroll
        for (int n = 0; n < 20; n++) acc += pa[n * 3] * pb[n * 6];
        sG1[o] = acc;
    }
    // G3[r3,m4,r4] = sum_n c1_3[a3,m4,n,a4] * c2_3[b3,n,0,b4]
    for (int o = tid; o < 324; o += NT) {
        int r4 = o % 9; int rest = o / 9;
        int m4 = rest % 4; int r3 = rest / 4;
        int a3 = r3 / 3, b3 = r3 % 3, a4 = r4 / 3, b4 = r4 % 3;
        const float* pa = c1_3 + (a3 * 4 + m4) * 60 + a4;      // n-stride 3
        const float* pb = c2_3 + b3 * 60 + b4;                 // n-stride 3
        float acc = 0.f;
        #pragma unroll
        for (int n = 0; n < 20; n++) acc += pa[n * 3] * pb[n * 3];
        sG3[o] = acc;
    }
    // G4[r4,m5] = sum_n c1_4[a4,m5,n,0] * c2_4[b4,n,0,0]
    for (int o = tid; o < 72; o += NT) {
        int m5 = o % 8, r4 = o / 8;
        int a4 = r4 / 3, b4 = r4 % 3;
        const float* pa = c1_4 + (a4 * 8 + m5) * 10;
        const float* pb = c2_4 + b4 * 10;
        float acc = 0.f;
        #pragma unroll
        for (int n = 0; n < 10; n++) acc += pa[n] * pb[n];
        sG4[r4 * 8 + m5] = acc;
    }
    // A1[r1] = sum_n c1_0[0,0,n,a1] * c2_0[0,n,0,b1]   (m1=0 only)
    if (tid < 9) {
        int a1 = tid / 3, b1 = tid % 3;
        float acc = 0.f;
        #pragma unroll
        for (int n = 0; n < 10; n++) acc += c1_0[n * 3 + a1] * c2_0[n * 3 + b1];
        sA1[tid] = acc;
    }
    __syncthreads();

    // ---------- Phase 1: G2 (72x45x50 matmul, 4x3 register tiles) + A2 ----------
    if (tid < 18) {  // A2[p2,r2] = sum_r1 A1[r1]*G1[r1,0,p2,r2]
        int r2 = tid % 9, p2 = tid / 9;
        float acc = 0.f;
        #pragma unroll
        for (int r1 = 0; r1 < 9; r1++)
            acc += sA1[r1] * sG1[(r1 * 8 + p2) * 9 + r2];
        sA2[p2 * 9 + r2] = acc;
    }
    for (int t = tid; t < 270; t += NT) {   // 18 u-tiles x 15 v-tiles
        int u0 = (t / 15) * 4, v0 = (t % 15) * 3;
        float acc[4][3] = {};
        int abase[4], bbase[3];
        #pragma unroll
        for (int i = 0; i < 4; i++) { int u = u0 + i; abase[i] = (u / 3) * 150 + (u % 3); }
        #pragma unroll
        for (int j = 0; j < 3; j++) { int v = v0 + j; bbase[j] = (v / 15) * 750 + (v % 15); }
        #pragma unroll 5
        for (int k = 0; k < 50; k++) {
            float a[4], b[3];
            #pragma unroll
            for (int i = 0; i < 4; i++) a[i] = sC1[abase[i] + k * 3];
            #pragma unroll
            for (int j = 0; j < 3; j++) b[j] = sC2[bbase[j] + k * 15];
            #pragma unroll
            for (int i = 0; i < 4; i++)
                #pragma unroll
                for (int j = 0; j < 3; j++) acc[i][j] += a[i] * b[j];
        }
        #pragma unroll
        for (int i = 0; i < 4; i++)
            #pragma unroll
            for (int j = 0; j < 3; j++) sG2[(u0 + i) * 45 + (v0 + j)] = acc[i][j];
    }
    __syncthreads();

    // ---------- Phase 2: A3[m3,c,r3] = sum_{a2,b2} A2[p2,(a2,b2)] * G2 ----------
    for (int o = tid; o < 720; o += NT) {
        int r3 = o % 9; int rest = o / 9;
        int c = rest % 10; int m3 = rest / 10;
        int p2 = c / 5, p3 = c % 5;
        int a3 = r3 / 3, b3 = r3 % 3;
        float acc = 0.f;
        #pragma unroll
        for (int a2 = 0; a2 < 3; a2++)
            #pragma unroll
            for (int b2 = 0; b2 < 3; b2++)
                acc += sA2[p2 * 9 + a2 * 3 + b2]
                     * sG2[(a2 * 24 + m3 * 3 + a3) * 45 + (b2 * 15 + p3 * 3 + b3)];
        sA3[o] = acc;
    }
    __syncthreads();

    // ---------- Phase 3: A4[m3,m4,c,r4] = sum_r3 A3[m3,c,r3]*G3[r3,m4,r4] ----------
    // (overwrites staged c1_2 region; it is dead now)
    for (int o = tid; o < 2880; o += NT) {
        int r4 = o % 9; int rest = o / 9;
        int c = rest % 10; rest /= 10;
        int m4 = rest % 4; int m3 = rest / 4;
        float acc = 0.f;
        #pragma unroll
        for (int r3 = 0; r3 < 9; r3++)
            acc += sA3[(m3 * 10 + c) * 9 + r3] * sG3[(r3 * 4 + m4) * 9 + r4];
        sA4[o] = acc;
    }
    __syncthreads();

    // ---------- Phase 4: W[j,c] = sum_r4 A4[m3,m4,c,r4]*G4[r4,m5], j=m3*32+m4*8+m5 ----------
    for (int o = tid; o < 2560; o += NT) {
        int c = o % 10; int j = o / 10;
        int m5 = j % 8; int m4 = (j / 8) % 4; int m3 = j / 32;
        float acc = 0.f;
        #pragma unroll
        for (int r4 = 0; r4 < 9; r4++)
            acc += sA4[((m3 * 4 + m4) * 10 + c) * 9 + r4] * sG4[r4 * 8 + m5];
        sW[o] = acc;
    }
    __syncthreads();

    // ---------- Phase 5: logits[b,c] = sum_{j<177} x[b,j] * W[j,c] ----------
    for (int o = tid; o < 640; o += NT) {
        int c = o % 10; int b = o / 10;
        const float* xr = x + b * 177;
        float acc = 0.f;
        #pragma unroll 3
        for (int j = 0; j < 177; j++)
            acc += xr[j] * sW[j * 10 + c];
        sLog[o] = acc;
    }
    __syncthreads();

    // ---------- Phase 6: log_softmax per row ----------
    if (tid < 64) {
        float v[10], m = -INFINITY;
        #pragma unroll
        for (int c = 0; c < 10; c++) { v[c] = sLog[tid * 10 + c]; m = fmaxf(m, v[c]); }
        float s = 0.f;
        #pragma unroll
        for (int c = 0; c < 10; c++) s += __expf(v[c] - m);
        float lse = m + __logf(s);
        #pragma unroll
        for (int c = 0; c < 10; c++) out[tid * 10 + c] = v[c] - lse;
    }
}

extern "C" void kernel_launch(void* const* d_in, const int* in_sizes, int n_in,
                              void* d_out, int out_size) {
    const float* x    = (const float*)d_in[0];
    const float* c1_0 = (const float*)d_in[1];
    const float* c1_1 = (const float*)d_in[2];
    const float* c1_2 = (const float*)d_in[3];
    const float* c1_3 = (const float*)d_in[4];
    const float* c1_4 = (const float*)d_in[5];
    const float* c2_0 = (const float*)d_in[6];
    const float* c2_1 = (const float*)d_in[7];
    const float* c2_2 = (const float*)d_in[8];
    const float* c2_3 = (const float*)d_in[9];
    const float* c2_4 = (const float*)d_in[10];
    float* out = (float*)d_out;

    tt_fused_kernel<<<1, NT>>>(x, c1_0, c1_1, c1_2, c1_3, c1_4,
                               c2_0, c2_1, c2_2, c2_3, c2_4, out);
}

// round 6
// speedup vs baseline: 2.2168x; 1.2750x over previous
#include <cuda_runtime.h>
#include <math.h>

#define NT 1024

// Fused TT-network:  y = log_softmax( x_pad @ W1_tt @ W2_tt )
// TT x TT (matching modes) = TT with cores G_k = contract_n(c1_k, c2_k),
// ranks kron'd (3*3=9). Zero-pad 177->3072 => only m1=m2=0 contribute =>
// effective dense weight is W[256,10]; only j<177 rows ever touched.
//
// Round-5 kernel (passing, 22.4us) with ONE change: phases 5+6 replaced by a
// shfl-tree GEMM+log_softmax using all 32 warps (16 lanes per batch row).
__global__ __launch_bounds__(NT) void tt_fused_kernel(
    const float* __restrict__ x,     // (64,177)
    const float* __restrict__ c1_0,  // (1,3,10,3)
    const float* __restrict__ c1_1,  // (3,4,20,3)
    const float* __restrict__ c1_2,  // (3,8,50,3)
    const float* __restrict__ c1_3,  // (3,4,20,3)
    const float* __restrict__ c1_4,  // (3,8,10,1)
    const float* __restrict__ c2_0,  // (1,10,1,3)
    const float* __restrict__ c2_1,  // (3,20,2,3)
    const float* __restrict__ c2_2,  // (3,50,5,3)
    const float* __restrict__ c2_3,  // (3,20,1,3)
    const float* __restrict__ c2_4,  // (3,10,1,1)
    float* __restrict__ out)         // (64,10)
{
    __shared__ float sG1[648];    // [r1(9), m2(4), p2(2), r2(9)]
    __shared__ float sG2[3240];   // [u(72) = (a2,m3,a3)] x [v(45) = (b2,p3,b3)]
    __shared__ float sG3[324];    // [r3(9), m4(4), r4(9)]
    __shared__ float sG4[72];     // [r4(9), m5(8)]
    __shared__ float sA1[9];
    __shared__ float sA2[18];     // [p2(2), r2(9)]
    __shared__ float sA3[720];    // [m3(8), c(10), r3(9)]
    __shared__ float sBUF[5850];  // phase A: sC1(3600)+sC2(2250); phase B: A4(2880)+W(2560)

    float* sC1 = sBUF;            // staged c1_2
    float* sC2 = sBUF + 3600;     // staged c2_2
    float* sA4 = sBUF;            // [m3(8), m4(4), c(10), r4(9)]  (reuses sC1 space)
    float* sW  = sBUF + 2880;     // [j(256), c(10)]               (reuses tail)

    const int tid = threadIdx.x;

    // ---------- Phase 0: stage big cores; build G1, G3, G4, A1 ----------
    for (int i = tid; i < 3600; i += NT) sC1[i] = c1_2[i];
    for (int i = tid; i < 2250; i += NT) sC2[i] = c2_2[i];

    // G1[r1,m2,p2,r2] = sum_n c1_1[a1,m2,n,a2] * c2_1[b1,n,p2,b2]
    for (int o = tid; o < 648; o += NT) {
        int r2 = o % 9; int rest = o / 9;
        int p2 = rest % 2; rest /= 2;
        int m2 = rest % 4; int r1 = rest / 4;
        int a1 = r1 / 3, b1 = r1 % 3, a2 = r2 / 3, b2 = r2 % 3;
        const float* pa = c1_1 + (a1 * 4 + m2) * 60 + a2;      // n-stride 3
        const float* pb = c2_1 + b1 * 120 + p2 * 3 + b2;       // n-stride 6
        float acc = 0.f;
        #pragma unroll
        for (int n = 0; n < 20; n++) acc += pa[n * 3] * pb[n * 6];
        sG1[o] = acc;
    }
    // G3[r3,m4,r4] = sum_n c1_3[a3,m4,n,a4] * c2_3[b3,n,0,b4]
    for (int o = tid; o < 324; o += NT) {
        int r4 = o % 9; int rest = o / 9;
        int m4 = rest % 4; int r3 = rest / 4;
        int a3 = r3 / 3, b3 = r3 % 3, a4 = r4 / 3, b4 = r4 % 3;
        const float* pa = c1_3 + (a3 * 4 + m4) * 60 + a4;      // n-stride 3
        const float* pb = c2_3 + b3 * 60 + b4;                 // n-stride 3
        float acc = 0.f;
        #pragma unroll
        for (int n = 0; n < 20; n++) acc += pa[n * 3] * pb[n * 3];
        sG3[o] = acc;
    }
    // G4[r4,m5] = sum_n c1_4[a4,m5,n,0] * c2_4[b4,n,0,0]
    for (int o = tid; o < 72; o += NT) {
        int m5 = o % 8, r4 = o / 8;
        int a4 = r4 / 3, b4 = r4 % 3;
        const float* pa = c1_4 + (a4 * 8 + m5) * 10;
        const float* pb = c2_4 + b4 * 10;
        float acc = 0.f;
        #pragma unroll
        for (int n = 0; n < 10; n++) acc += pa[n] * pb[n];
        sG4[r4 * 8 + m5] = acc;
    }
    // A1[r1] = sum_n c1_0[0,0,n,a1] * c2_0[0,n,0,b1]   (m1=0 only)
    if (tid < 9) {
        int a1 = tid / 3, b1 = tid % 3;
        float acc = 0.f;
        #pragma unroll
        for (int n = 0; n < 10; n++) acc += c1_0[n * 3 + a1] * c2_0[n * 3 + b1];
        sA1[tid] = acc;
    }
    __syncthreads();

    // ---------- Phase 1: G2 (72x45x50 matmul, 4x3 register tiles) + A2 ----------
    if (tid < 18) {  // A2[p2,r2] = sum_r1 A1[r1]*G1[r1,0,p2,r2]
        int r2 = tid % 9, p2 = tid / 9;
        float acc = 0.f;
        #pragma unroll
        for (int r1 = 0; r1 < 9; r1++)
            acc += sA1[r1] * sG1[(r1 * 8 + p2) * 9 + r2];
        sA2[p2 * 9 + r2] = acc;
    }
    for (int t = tid; t < 270; t += NT) {   // 18 u-tiles x 15 v-tiles
        int u0 = (t / 15) * 4, v0 = (t % 15) * 3;
        float acc[4][3] = {};
        int abase[4], bbase[3];
        #pragma unroll
        for (int i = 0; i < 4; i++) { int u = u0 + i; abase[i] = (u / 3) * 150 + (u % 3); }
        #pragma unroll
        for (int j = 0; j < 3; j++) { int v = v0 + j; bbase[j] = (v / 15) * 750 + (v % 15); }
        #pragma unroll 5
        for (int k = 0; k < 50; k++) {
            float a[4], b[3];
            #pragma unroll
            for (int i = 0; i < 4; i++) a[i] = sC1[abase[i] + k * 3];
            #pragma unroll
            for (int j = 0; j < 3; j++) b[j] = sC2[bbase[j] + k * 15];
            #pragma unroll
            for (int i = 0; i < 4; i++)
                #pragma unroll
                for (int j = 0; j < 3; j++) acc[i][j] += a[i] * b[j];
        }
        #pragma unroll
        for (int i = 0; i < 4; i++)
            #pragma unroll
            for (int j = 0; j < 3; j++) sG2[(u0 + i) * 45 + (v0 + j)] = acc[i][j];
    }
    __syncthreads();

    // ---------- Phase 2: A3[m3,c,r3] = sum_{a2,b2} A2[p2,(a2,b2)] * G2 ----------
    for (int o = tid; o < 720; o += NT) {
        int r3 = o % 9; int rest = o / 9;
        int c = rest % 10; int m3 = rest / 10;
        int p2 = c / 5, p3 = c % 5;
        int a3 = r3 / 3, b3 = r3 % 3;
        float acc = 0.f;
        #pragma unroll
        for (int a2 = 0; a2 < 3; a2++)
            #pragma unroll
            for (int b2 = 0; b2 < 3; b2++)
                acc += sA2[p2 * 9 + a2 * 3 + b2]
                     * sG2[(a2 * 24 + m3 * 3 + a3) * 45 + (b2 * 15 + p3 * 3 + b3)];
        sA3[o] = acc;
    }
    __syncthreads();

    // ---------- Phase 3: A4[m3,m4,c,r4] = sum_r3 A3[m3,c,r3]*G3[r3,m4,r4] ----------
    // (overwrites staged c1_2 region; it is dead now)
    for (int o = tid; o < 2880; o += NT) {
        int r4 = o % 9; int rest = o / 9;
        int c = rest % 10; rest /= 10;
        int m4 = rest % 4; int m3 = rest / 4;
        float acc = 0.f;
        #pragma unroll
        for (int r3 = 0; r3 < 9; r3++)
            acc += sA3[(m3 * 10 + c) * 9 + r3] * sG3[(r3 * 4 + m4) * 9 + r4];
        sA4[o] = acc;
    }
    __syncthreads();

    // ---------- Phase 4: W[j,c] = sum_r4 A4[m3,m4,c,r4]*G4[r4,m5], j=m3*32+m4*8+m5 ----------
    for (int o = tid; o < 2560; o += NT) {
        int c = o % 10; int j = o / 10;
        int m5 = j % 8; int m4 = (j / 8) % 4; int m3 = j / 32;
        float acc = 0.f;
        #pragma unroll
        for (int r4 = 0; r4 < 9; r4++)
            acc += sA4[((m3 * 4 + m4) * 10 + c) * 9 + r4] * sG4[r4 * 8 + m5];
        sW[o] = acc;
    }
    __syncthreads();

    // ---------- Phase 5: logits + log_softmax, 16 lanes per batch row ------
    // b = tid/16, lane s strides j by 16; x read once, coalesced; 4-step
    // shfl tree (width 16) then fused log_softmax in lane 0.
    {
        int b = tid >> 4, s = tid & 15;
        const float* xr = x + b * 177;
        float acc[10];
        #pragma unroll
        for (int c = 0; c < 10; c++) acc[c] = 0.f;
        for (int j = s; j < 177; j += 16) {
            float xv = __ldg(xr + j);
            const float* wr = sW + j * 10;
            #pragma unroll
            for (int c = 0; c < 10; c++) acc[c] = fmaf(xv, wr[c], acc[c]);
        }
        #pragma unroll
        for (int off = 8; off > 0; off >>= 1)
            #pragma unroll
            for (int c = 0; c < 10; c++)
                acc[c] += __shfl_down_sync(0xffffffffu, acc[c], off, 16);
        if (s == 0) {
            float m = -INFINITY;
            #pragma unroll
            for (int c = 0; c < 10; c++) m = fmaxf(m, acc[c]);
            float sum = 0.f;
            #pragma unroll
            for (int c = 0; c < 10; c++) sum += __expf(acc[c] - m);
            float lse = m + __logf(sum);
            #pragma unroll
            for (int c = 0; c < 10; c++) out[b * 10 + c] = acc[c] - lse;
        }
    }
}

extern "C" void kernel_launch(void* const* d_in, const int* in_sizes, int n_in,
                              void* d_out, int out_size) {
    const float* x    = (const float*)d_in[0];
    const float* c1_0 = (const float*)d_in[1];
    const float* c1_1 = (const float*)d_in[2];
    const float* c1_2 = (const float*)d_in[3];
    const float* c1_3 = (const float*)d_in[4];
    const float* c1_4 = (const float*)d_in[5];
    const float* c2_0 = (const float*)d_in[6];
    const float* c2_1 = (const float*)d_in[7];
    const float* c2_2 = (const float*)d_in[8];
    const float* c2_3 = (const float*)d_in[9];
    const float* c2_4 = (const float*)d_in[10];
    float* out = (float*)d_out;

    tt_fused_kernel<<<1, NT>>>(x, c1_0, c1_1, c1_2, c1_3, c1_4,
                               c2_0, c2_1, c2_2, c2_3, c2_4, out);
}

// round 7
// speedup vs baseline: 2.5894x; 1.1681x over previous
#include <cuda_runtime.h>
#include <math.h>

#define NT 1024

// Fused TT-network:  y = log_softmax( x_pad @ W1_tt @ W2_tt )
// TT x TT (matching modes) = TT with cores G_k = contract_n(c1_k, c2_k),
// ranks kron'd (3*3=9). Zero-pad 177->3072 => only m1=m2=0 contribute =>
// effective dense weight W[256,10]; only j<177 rows touched.
//
// R7 changes vs proven R6: (1) x prefetched to registers at kernel top,
// (2) G1 computed only for m2=0 (all that's ever used), (3) G34 = G3*G4
// precomputed in phase 1 -> A4 phase and one barrier deleted.
__global__ __launch_bounds__(NT) void tt_fused_kernel(
    const float* __restrict__ x,     // (64,177)
    const float* __restrict__ c1_0,  // (1,3,10,3)
    const float* __restrict__ c1_1,  // (3,4,20,3)
    const float* __restrict__ c1_2,  // (3,8,50,3)
    const float* __restrict__ c1_3,  // (3,4,20,3)
    const float* __restrict__ c1_4,  // (3,8,10,1)
    const float* __restrict__ c2_0,  // (1,10,1,3)
    const float* __restrict__ c2_1,  // (3,20,2,3)
    const float* __restrict__ c2_2,  // (3,50,5,3)
    const float* __restrict__ c2_3,  // (3,20,1,3)
    const float* __restrict__ c2_4,  // (3,10,1,1)
    float* __restrict__ out)         // (64,10)
{
    __shared__ float sG1[162];    // [r1(9), p2(2), r2(9)]  (m2=0 slice only)
    __shared__ float sG2[3240];   // [u(72)=(a2,m3,a3)] x [v(45)=(b2,p3,b3)]
    __shared__ float sG3[324];    // [r3(9), m4(4), r4(9)]
    __shared__ float sG4[72];     // [r4(9), m5(8)]
    __shared__ float sG34[288];   // [r3(9), m4(4), m5(8)]
    __shared__ float sA1[9];
    __shared__ float sA2[18];     // [p2(2), r2(9)]
    __shared__ float sA3[720];    // [m3(8), c(10), r3(9)]
    __shared__ float sBUF[5850];  // A: sC1(3600)+sC2(2250); B: W(2560) in tail

    float* sC1 = sBUF;            // staged c1_2
    float* sC2 = sBUF + 3600;     // staged c2_2
    float* sW  = sBUF + 2880;     // [j(256), c(10)] (staging dead by then)

    const int tid = threadIdx.x;

    // ---------- x prefetch: issue LDGs now, consume in phase 5 ----------
    const int b5 = tid >> 4, s5 = tid & 15;
    float xv[12];
    {
        const float* xr = x + b5 * 177;
        #pragma unroll
        for (int k = 0; k < 12; k++) {
            int j = s5 + 16 * k;
            xv[k] = (j < 177) ? __ldg(xr + j) : 0.f;
        }
    }

    // ---------- Phase 0: stage big cores; G1_0, G3, G4, A1 (disjoint tids) --
    for (int i = tid; i < 3600; i += NT) sC1[i] = c1_2[i];
    for (int i = tid; i < 2250; i += NT) sC2[i] = c2_2[i];

    if (tid < 162) {
        // G1_0[r1,p2,r2] = sum_n c1_1[a1,0,n,a2] * c2_1[b1,n,p2,b2]
        int o = tid;
        int r2 = o % 9, p2 = (o / 9) % 2, r1 = o / 18;
        int a1 = r1 / 3, b1 = r1 % 3, a2 = r2 / 3, b2 = r2 % 3;
        const float* pa = c1_1 + a1 * 240 + a2;          // m2=0, n-stride 3
        const float* pb = c2_1 + b1 * 120 + p2 * 3 + b2; // n-stride 6
        float acc = 0.f;
        #pragma unroll
        for (int n = 0; n < 20; n++) acc += pa[n * 3] * pb[n * 6];
        sG1[(r1 * 2 + p2) * 9 + r2] = acc;
    } else if (tid < 486) {
        // G3[r3,m4,r4] = sum_n c1_3[a3,m4,n,a4] * c2_3[b3,n,0,b4]  (324)
        int o = tid - 162;
        int r4 = o % 9; int rest = o / 9;
        int m4 = rest % 4; int r3 = rest / 4;
        int a3 = r3 / 3, b3 = r3 % 3, a4 = r4 / 3, b4 = r4 % 3;
        const float* pa = c1_3 + (a3 * 4 + m4) * 60 + a4;  // n-stride 3
        const float* pb = c2_3 + b3 * 60 + b4;             // n-stride 3
        float acc = 0.f;
        #pragma unroll
        for (int n = 0; n < 20; n++) acc += pa[n * 3] * pb[n * 3];
        sG3[o] = acc;
    } else if (tid < 558) {
        // G4[r4,m5] = sum_n c1_4[a4,m5,n,0] * c2_4[b4,n,0,0]  (72)
        int o = tid - 486;
        int m5 = o % 8, r4 = o / 8;
        int a4 = r4 / 3, b4 = r4 % 3;
        const float* pa = c1_4 + (a4 * 8 + m5) * 10;
        const float* pb = c2_4 + b4 * 10;
        float acc = 0.f;
        #pragma unroll
        for (int n = 0; n < 10; n++) acc += pa[n] * pb[n];
        sG4[r4 * 8 + m5] = acc;
    } else if (tid < 567) {
        // A1[r1] = sum_n c1_0[0,0,n,a1] * c2_0[0,n,0,b1]  (m1=0 only)
        int r1 = tid - 558;
        int a1 = r1 / 3, b1 = r1 % 3;
        float acc = 0.f;
        #pragma unroll
        for (int n = 0; n < 10; n++) acc += c1_0[n * 3 + a1] * c2_0[n * 3 + b1];
        sA1[r1] = acc;
    }
    __syncthreads();

    // ---------- Phase 1: G2 (4x3 reg tiles) | G34 | A2  (disjoint tids) ----
    if (tid < 270) {
        int t = tid;
        int u0 = (t / 15) * 4, v0 = (t % 15) * 3;
        float acc[4][3] = {};
        int abase[4], bbase[3];
        #pragma unroll
        for (int i = 0; i < 4; i++) { int u = u0 + i; abase[i] = (u / 3) * 150 + (u % 3); }
        #pragma unroll
        for (int j = 0; j < 3; j++) { int v = v0 + j; bbase[j] = (v / 15) * 750 + (v % 15); }
        #pragma unroll 5
        for (int k = 0; k < 50; k++) {
            float a[4], b[3];
            #pragma unroll
            for (int i = 0; i < 4; i++) a[i] = sC1[abase[i] + k * 3];
            #pragma unroll
            for (int j = 0; j < 3; j++) b[j] = sC2[bbase[j] + k * 15];
            #pragma unroll
            for (int i = 0; i < 4; i++)
                #pragma unroll
                for (int j = 0; j < 3; j++) acc[i][j] += a[i] * b[j];
        }
        #pragma unroll
        for (int i = 0; i < 4; i++)
            #pragma unroll
            for (int j = 0; j < 3; j++) sG2[(u0 + i) * 45 + (v0 + j)] = acc[i][j];
    } else if (tid < 558) {
        // G34[r3,m4,m5] = sum_r4 G3[r3,m4,r4] * G4[r4,m5]  (288)
        int o = tid - 270;
        int m5 = o % 8; int m4 = (o / 8) % 4; int r3 = o / 32;
        float acc = 0.f;
        #pragma unroll
        for (int r4 = 0; r4 < 9; r4++)
            acc += sG3[(r3 * 4 + m4) * 9 + r4] * sG4[r4 * 8 + m5];
        sG34[(r3 * 4 + m4) * 8 + m5] = acc;
    } else if (tid < 576) {
        // A2[p2,r2] = sum_r1 A1[r1] * G1_0[r1,p2,r2]
        int o = tid - 558;
        int r2 = o % 9, p2 = o / 9;
        float acc = 0.f;
        #pragma unroll
        for (int r1 = 0; r1 < 9; r1++)
            acc += sA1[r1] * sG1[(r1 * 2 + p2) * 9 + r2];
        sA2[p2 * 9 + r2] = acc;
    }
    __syncthreads();

    // ---------- Phase 2: A3[m3,c,r3] = sum_{a2,b2} A2[p2,(a2,b2)] * G2 -----
    if (tid < 720) {
        int o = tid;
        int r3 = o % 9; int rest = o / 9;
        int c = rest % 10; int m3 = rest / 10;
        int p2 = c / 5, p3 = c % 5;
        int a3 = r3 / 3, b3 = r3 % 3;
        float acc = 0.f;
        #pragma unroll
        for (int a2 = 0; a2 < 3; a2++)
            #pragma unroll
            for (int b2 = 0; b2 < 3; b2++)
                acc += sA2[p2 * 9 + a2 * 3 + b2]
                     * sG2[(a2 * 24 + m3 * 3 + a3) * 45 + (b2 * 15 + p3 * 3 + b3)];
        sA3[o] = acc;
    }
    __syncthreads();

    // ---------- Phase 3: W[j,c] = sum_r3 A3[m3,c,r3] * G34[r3,m4,m5] -------
    for (int o = tid; o < 2560; o += NT) {
        int c = o % 10; int j = o / 10;
        int m5 = j % 8; int m4 = (j / 8) % 4; int m3 = j / 32;
        float acc = 0.f;
        #pragma unroll
        for (int r3 = 0; r3 < 9; r3++)
            acc += sA3[(m3 * 10 + c) * 9 + r3] * sG34[(r3 * 4 + m4) * 8 + m5];
        sW[o] = acc;
    }
    __syncthreads();

    // ---------- Phase 4: logits + log_softmax from prefetched x ------------
    {
        float acc[10];
        #pragma unroll
        for (int c = 0; c < 10; c++) acc[c] = 0.f;
        #pragma unroll
        for (int k = 0; k < 12; k++) {
            int j = s5 + 16 * k;                 // j <= 191 < 256: sW valid
            const float* wr = sW + j * 10;
            float xvk = xv[k];                   // 0 for j >= 177
            #pragma unroll
            for (int c = 0; c < 10; c++) acc[c] = fmaf(xvk, wr[c], acc[c]);
        }
        #pragma unroll
        for (int off = 8; off > 0; off >>= 1)
            #pragma unroll
            for (int c = 0; c < 10; c++)
                acc[c] += __shfl_down_sync(0xffffffffu, acc[c], off, 16);
        if (s5 == 0) {
            float m = -INFINITY;
            #pragma unroll
            for (int c = 0; c < 10; c++) m = fmaxf(m, acc[c]);
            float sum = 0.f;
            #pragma unroll
            for (int c = 0; c < 10; c++) sum += __expf(acc[c] - m);
            float lse = m + __logf(sum);
            #pragma unroll
            for (int c = 0; c < 10; c++) out[b5 * 10 + c] = acc[c] - lse;
        }
    }
}

extern "C" void kernel_launch(void* const* d_in, const int* in_sizes, int n_in,
                              void* d_out, int out_size) {
    const float* x    = (const float*)d_in[0];
    const float* c1_0 = (const float*)d_in[1];
    const float* c1_1 = (const float*)d_in[2];
    const float* c1_2 = (const float*)d_in[3];
    const float* c1_3 = (const float*)d_in[4];
    const float* c1_4 = (const float*)d_in[5];
    const float* c2_0 = (const float*)d_in[6];
    const float* c2_1 = (const float*)d_in[7];
    const float* c2_2 = (const float*)d_in[8];
    const float* c2_3 = (const float*)d_in[9];
    const float* c2_4 = (const float*)d_in[10];
    float* out = (float*)d_out;

    tt_fused_kernel<<<1, NT>>>(x, c1_0, c1_1, c1_2, c1_3, c1_4,
                               c2_0, c2_1, c2_2, c2_3, c2_4, out);
}